// round 15
// baseline (speedup 1.0000x reference)
#include <cuda_runtime.h>
#include <math.h>

// Problem constants
#define B_DIM 64
#define S_DIM 4096
#define C_DIM 128
#define N2 2048          // half-length complex FFT size
#define NT 256
#define TOPK 64

// 128 MB scratch in (B, C, S) layout
__device__ float g_scratch[(size_t)B_DIM * C_DIM * S_DIM];
// Twiddle table in global: g_tw[t] = (cos(pi t/2048), sin(pi t/2048))
__device__ float2 g_tw[N2];

typedef unsigned long long u64;

__device__ __forceinline__ float2 cmul(float2 a, float2 b) {
    return make_float2(a.x * b.x - a.y * b.y, a.x * b.y + a.y * b.x);
}

// ---- packed f32x2 ops (Blackwell FADD2/FFMA2/FMUL2). Bit-identical per lane
// to the scalar versions (fma(b,-1,a) rounds once to the exact a-b). ----
__device__ __forceinline__ float2 padd(float2 a, float2 b) {
    u64 pa, pb, pc;
    asm("mov.b64 %0, {%1,%2};" : "=l"(pa) : "f"(a.x), "f"(a.y));
    asm("mov.b64 %0, {%1,%2};" : "=l"(pb) : "f"(b.x), "f"(b.y));
    asm("add.rn.f32x2 %0, %1, %2;" : "=l"(pc) : "l"(pa), "l"(pb));
    float2 r;
    asm("mov.b64 {%0,%1}, %2;" : "=f"(r.x), "=f"(r.y) : "l"(pc));
    return r;
}
__device__ __forceinline__ float2 psub(float2 a, float2 b) {
    u64 pa, pb, pc;
    asm("mov.b64 %0, {%1,%2};" : "=l"(pa) : "f"(a.x), "f"(a.y));
    asm("mov.b64 %0, {%1,%2};" : "=l"(pb) : "f"(b.x), "f"(b.y));
    asm("fma.rn.f32x2 %0, %1, %2, %3;"
        : "=l"(pc) : "l"(pb), "l"(0xBF800000BF800000ull), "l"(pa));
    float2 r;
    asm("mov.b64 {%0,%1}, %2;" : "=f"(r.x), "=f"(r.y) : "l"(pc));
    return r;
}
__device__ __forceinline__ float2 pmul(float2 a, float2 b) {
    u64 pa, pb, pc;
    asm("mov.b64 %0, {%1,%2};" : "=l"(pa) : "f"(a.x), "f"(a.y));
    asm("mov.b64 %0, {%1,%2};" : "=l"(pb) : "f"(b.x), "f"(b.y));
    asm("mul.rn.f32x2 %0, %1, %2;" : "=l"(pc) : "l"(pa), "l"(pb));
    float2 r;
    asm("mov.b64 {%0,%1}, %2;" : "=f"(r.x), "=f"(r.y) : "l"(pc));
    return r;
}

// Bank swizzle: bijective on [0,2048); conflict-free for all Stockham
// radix-8 patterns used here (stride-8 scatter, blocked scatter, consecutive).
__device__ __forceinline__ int SW(int i) { return i ^ (i >> 3); }

// Bit-exact mag^2 (used for both ranking values and the tie re-check).
__device__ __forceinline__ unsigned mag2u(float2 x) {
    return __float_as_uint(__fadd_rn(__fmul_rn(x.x, x.x), __fmul_rn(x.y, x.y)));
}

// ---------------------------------------------------------------------------
__global__ void __launch_bounds__(256) init_tw_kernel() {
    int t = blockIdx.x * 256 + threadIdx.x;
    float s, c;
    sincospif((float)t * (1.0f / 2048.0f), &s, &c);
    g_tw[t] = make_float2(c, s);
}

// ---------------------------------------------------------------------------
// Transposes, float4 on both global sides. At the structural HBM ceiling
// (~62% of spec) for this mixed gather/scatter pattern — leave alone.
// ---------------------------------------------------------------------------
__global__ void __launch_bounds__(256) transpose_in_kernel(const float* __restrict__ in) {
    __shared__ float tile[32][33];           // tile[channel][s]
    const int b = blockIdx.z;
    const int c0 = blockIdx.x * 32;          // channel tile
    const int r0 = blockIdx.y * 32;          // s tile
    const int tx = threadIdx.x;              // 0..7
    const int ty = threadIdx.y;              // 0..31
    const float* inb = in + (size_t)b * S_DIM * C_DIM;
    float* outb = g_scratch + (size_t)b * S_DIM * C_DIM;

    float4 v = *(const float4*)&inb[(size_t)(r0 + ty) * C_DIM + (c0 + 4 * tx)];
    tile[4 * tx + 0][ty] = v.x;
    tile[4 * tx + 1][ty] = v.y;
    tile[4 * tx + 2][ty] = v.z;
    tile[4 * tx + 3][ty] = v.w;
    __syncthreads();
    float4 w;
    w.x = tile[ty][4 * tx + 0];
    w.y = tile[ty][4 * tx + 1];
    w.z = tile[ty][4 * tx + 2];
    w.w = tile[ty][4 * tx + 3];
    *(float4*)&outb[(size_t)(c0 + ty) * S_DIM + (r0 + 4 * tx)] = w;
}

__global__ void __launch_bounds__(256) transpose_out_kernel(float* __restrict__ out) {
    __shared__ float tile[32][33];           // tile[s][channel]
    const int b = blockIdx.z;
    const int s0 = blockIdx.x * 32;          // s tile
    const int ch0 = blockIdx.y * 32;         // channel tile
    const int tx = threadIdx.x;              // 0..7
    const int ty = threadIdx.y;              // 0..31
    const float* inb = g_scratch + (size_t)b * S_DIM * C_DIM;
    float* outb = out + (size_t)b * S_DIM * C_DIM;

    float4 v = *(const float4*)&inb[(size_t)(ch0 + ty) * S_DIM + (s0 + 4 * tx)];
    tile[4 * tx + 0][ty] = v.x;
    tile[4 * tx + 1][ty] = v.y;
    tile[4 * tx + 2][ty] = v.z;
    tile[4 * tx + 3][ty] = v.w;
    __syncthreads();
    float4 w;
    w.x = tile[ty][4 * tx + 0];
    w.y = tile[ty][4 * tx + 1];
    w.z = tile[ty][4 * tx + 2];
    w.w = tile[ty][4 * tx + 3];
    *(float4*)&outb[(size_t)(s0 + ty) * C_DIM + (ch0 + 4 * tx)] = w;
}

// ---------------------------------------------------------------------------
// Radix-8 butterfly. Forward: omega = e^{-2pi i/8}; inverse: conjugate.
// Pure add/sub layers use packed f32x2 (bit-identical).
// ---------------------------------------------------------------------------
template<bool INV>
__device__ __forceinline__ void bfly8(const float2* a, float2* b) {
    const float r = 0.70710678118654752440f;
    float2 s0 = padd(a[0], a[4]), s1 = psub(a[0], a[4]);
    float2 s2 = padd(a[2], a[6]), s3 = psub(a[2], a[6]);
    float2 s4 = padd(a[1], a[5]), s5 = psub(a[1], a[5]);
    float2 s6 = padd(a[3], a[7]), s7 = psub(a[3], a[7]);
    float2 E0 = padd(s0, s2), E2 = psub(s0, s2);
    float2 O0 = padd(s4, s6), O2 = psub(s4, s6);
    float2 E1, E3, O1, O3;
    if (!INV) {
        E1 = make_float2(s1.x + s3.y, s1.y - s3.x);   // s1 - i s3
        E3 = make_float2(s1.x - s3.y, s1.y + s3.x);
        O1 = make_float2(s5.x + s7.y, s5.y - s7.x);
        O3 = make_float2(s5.x - s7.y, s5.y + s7.x);
    } else {
        E1 = make_float2(s1.x - s3.y, s1.y + s3.x);   // s1 + i s3
        E3 = make_float2(s1.x + s3.y, s1.y - s3.x);
        O1 = make_float2(s5.x - s7.y, s5.y + s7.x);
        O3 = make_float2(s5.x + s7.y, s5.y - s7.x);
    }
    b[0] = padd(E0, O0);
    b[4] = psub(E0, O0);
    float2 w1O, w3O;
    if (!INV) {
        w1O = make_float2(r * (O1.x + O1.y), r * (O1.y - O1.x));   // e^{-i pi/4} O1
        w3O = make_float2(r * (O3.y - O3.x), -r * (O3.x + O3.y));  // e^{-3i pi/4} O3
        b[2] = make_float2(E2.x + O2.y, E2.y - O2.x);              // E2 - i O2
        b[6] = make_float2(E2.x - O2.y, E2.y + O2.x);
    } else {
        w1O = make_float2(r * (O1.x - O1.y), r * (O1.x + O1.y));   // e^{+i pi/4} O1
        w3O = make_float2(-r * (O3.x + O3.y), r * (O3.x - O3.y));  // e^{+3i pi/4} O3
        b[2] = make_float2(E2.x - O2.y, E2.y + O2.x);              // E2 + i O2
        b[6] = make_float2(E2.x + O2.y, E2.y - O2.x);
    }
    b[1] = padd(E1, w1O);
    b[5] = psub(E1, w1O);
    b[3] = padd(E3, w3O);
    b[7] = psub(E3, w3O);
}

// Log-depth twiddle powers + scatter stores: dependency depth 3 cmuls.
#define SCATTER_W_TREE(dst, o, STRIDE, b, w1)                          \
    do {                                                               \
        float2 _w2 = cmul(w1, w1);                                     \
        float2 _w3 = cmul(_w2, w1);                                    \
        float2 _w4 = cmul(_w2, _w2);                                   \
        (dst)[SW((o))]              = (b)[0];                          \
        (dst)[SW((o) + (STRIDE))]   = cmul((b)[1], w1);                \
        (dst)[SW((o) + 2*(STRIDE))] = cmul((b)[2], _w2);               \
        (dst)[SW((o) + 3*(STRIDE))] = cmul((b)[3], _w3);               \
        (dst)[SW((o) + 4*(STRIDE))] = cmul((b)[4], _w4);               \
        (dst)[SW((o) + 5*(STRIDE))] = cmul((b)[5], cmul(_w4, w1));     \
        (dst)[SW((o) + 6*(STRIDE))] = cmul((b)[6], cmul(_w4, _w2));    \
        (dst)[SW((o) + 7*(STRIDE))] = cmul((b)[7], cmul(_w4, _w3));    \
    } while (0)

// Generic radix-8 Stockham stage, smem->smem, swizzled, one butterfly/thread.
template<int L, bool INV>
__device__ __forceinline__ void r8_stage(const float2* __restrict__ src,
                                         float2* __restrict__ dst,
                                         const float2* __restrict__ TW) {
    const int i = threadIdx.x;           // 256 butterflies
    const int k = i & (L - 1);
    const int u = i - k;
    float2 a[8], b[8];
#pragma unroll
    for (int m = 0; m < 8; ++m) a[m] = src[SW(i + 256 * m)];
    bfly8<INV>(a, b);
    float2 w1 = TW[2 * u];
    if (!INV) w1.y = -w1.y;
    const int o = 8 * u + k;
    SCATTER_W_TREE(dst, o, L, b, w1);
}

// First forward radix-8 stage (L=1), reading coalesced from global row.
__device__ __forceinline__ void r8_first_fwd(const float2* __restrict__ g,
                                             float2* __restrict__ dst,
                                             const float2* __restrict__ TW) {
    const int i = threadIdx.x;
    float2 a[8], b[8];
#pragma unroll
    for (int m = 0; m < 8; ++m) a[m] = g[i + 256 * m];
    bfly8<false>(a, b);
    float2 w1 = TW[2 * i]; w1.y = -w1.y;
    const int o = 8 * i;
    SCATTER_W_TREE(dst, o, 1, b, w1);
}

// Hermitian pair: given Z[k] (=a) and Z[2048-k] (=b), produce X[k], X[2048-k].
__device__ __forceinline__ void herm_pair(float2* __restrict__ X,
                                          const float2* __restrict__ TW,
                                          int k, float2 a, float2 b,
                                          unsigned& m1, unsigned& m2) {
    float2 fe = make_float2(0.5f * (a.x + b.x), 0.5f * (a.y - b.y));
    float2 d  = make_float2(0.5f * (a.x - b.x), 0.5f * (a.y + b.y));
    float2 w  = make_float2(TW[k].x, -TW[k].y);        // e^{-i 2pi k/4096}
    float2 wd = cmul(w, d);
    float2 x1 = make_float2(fe.x + wd.y, fe.y - wd.x);
    float2 x2 = make_float2(fe.x - wd.y, -fe.y - wd.x);
    X[k] = x1;
    X[2048 - k] = x2;
    m1 = mag2u(x1);
    m2 = mag2u(x2);
}

// Keep decision from the register-held mag^2 u of bin `bin`. Tie path reads X
// (unmodified at this point) for lowest-index-first rank, matching lax.top_k.
__device__ __forceinline__ bool decide_keep(const float2* __restrict__ X,
                                            unsigned u, int bin,
                                            unsigned thr, bool exact, int need) {
    if (exact) return u >= thr;
    if (u > thr) return true;
    if (u == thr) {
        int r = 0;
        for (int j = 0; j < bin; ++j)
            r += (mag2u(X[j]) == thr);
        return r < need;
    }
    return false;
}

// ---------------------------------------------------------------------------
// Per-row FFT + top-k + inverse FFT.
// Shared layout (dynamic, floats):
//   A  [2049 float2] @ 0      swizzled ping buffer; X aliases it identity-idx
//   Bb [2048 float2] @ 4098   swizzled pong buffer
// = 8194 floats = 32776 bytes.  Static: ws[2][8].
// ---------------------------------------------------------------------------
__global__ void __launch_bounds__(NT, 5) fft_topk_kernel() {
    extern __shared__ float sh[];
    float2* A  = (float2*)sh;            // 2049 entries
    float2* Bb = (float2*)(sh + 4098);   // 2048 entries
    float2* X  = A;                      // identity-indexed (2049 entries)
    const float2* TW = g_tw;
    __shared__ unsigned ws[2][8];

    const int tid = threadIdx.x;
    float* rowp = g_scratch + (size_t)blockIdx.x * S_DIM;
    const float2* gz = (const float2*)rowp;

    // ---- forward FFT: 3 radix-8 stages ----
    r8_first_fwd(gz, Bb, TW);        __syncthreads();
    r8_stage<8,  false>(Bb, A,  TW); __syncthreads();
    r8_stage<64, false>(A,  Bb, TW); __syncthreads();

    // ---- fused final radix-4 (twiddle-free) + Hermitian pair unpack ----
    // Thread t computes butterflies t and 512-t (t=0: 0 and 256); their 8
    // bins contain all four Hermitian pairs, so X is written from registers.
    unsigned mv[9];
#pragma unroll
    for (int q = 0; q < 9; ++q) mv[q] = 0u;
    unsigned vm = 0u;
    const int t = tid;
    // Bin indices owned by this thread (match herm_pair calls below).
    const int b0 = t;
    const int b1 = 2048 - t;
    const int b2 = t + 512;
    const int b3 = 1536 - t;
    const int b4 = (t == 0) ? 256  : 1024 - t;
    const int b5 = (t == 0) ? 1792 : 1024 + t;
    const int b6 = (t == 0) ? 768  : 512 - t;
    const int b7 = (t == 0) ? 1280 : 1536 + t;
    {
        const int bfa = t;
        const int bfb = (t == 0) ? 256 : 512 - t;
        float2 c0, c1, c2, c3, e0, e1, e2, e3;
        {
            float2 a0 = Bb[SW(bfa)],        a1 = Bb[SW(bfa + 512)],
                   a2 = Bb[SW(bfa + 1024)], a3 = Bb[SW(bfa + 1536)];
            float2 t0 = padd(a0, a2), t1 = psub(a0, a2);
            float2 t2 = padd(a1, a3), t3 = psub(a1, a3);
            c0 = padd(t0, t2);
            c1 = make_float2(t1.x + t3.y, t1.y - t3.x);   // t1 - i t3
            c2 = psub(t0, t2);
            c3 = make_float2(t1.x - t3.y, t1.y + t3.x);   // t1 + i t3
        }
        {
            float2 a0 = Bb[SW(bfb)],        a1 = Bb[SW(bfb + 512)],
                   a2 = Bb[SW(bfb + 1024)], a3 = Bb[SW(bfb + 1536)];
            float2 t0 = padd(a0, a2), t1 = psub(a0, a2);
            float2 t2 = padd(a1, a3), t3 = psub(a1, a3);
            e0 = padd(t0, t2);
            e1 = make_float2(t1.x + t3.y, t1.y - t3.x);
            e2 = psub(t0, t2);
            e3 = make_float2(t1.x - t3.y, t1.y + t3.x);
        }
        if (t > 0) {
            herm_pair(X, TW, t,        c0, e3, mv[0], mv[1]);
            herm_pair(X, TW, t + 512,  c1, e2, mv[2], mv[3]);
            herm_pair(X, TW, 1024 - t, e1, c2, mv[4], mv[5]);
            herm_pair(X, TW, 512 - t,  e0, c3, mv[6], mv[7]);
        } else {
            herm_pair(X, TW, 0,   c0, c0, mv[0], mv[1]);
            herm_pair(X, TW, 512, c1, c3, mv[2], mv[3]);
            herm_pair(X, TW, 256, e0, e3, mv[4], mv[5]);
            herm_pair(X, TW, 768, e1, e2, mv[6], mv[7]);
            float2 x = make_float2(c2.x, -c2.y);          // k=1024: conj(Z[1024])
            X[1024] = x;
            mv[8] = mag2u(x);
        }
#pragma unroll
        for (int q = 0; q < 9; ++q) vm = max(vm, mv[q]);
    }
    // block max seed (one barrier serves X writes + ws writes)
    vm = __reduce_max_sync(0xffffffffu, vm);
    if ((tid & 31) == 0) ws[1][tid >> 5] = vm;
    __syncthreads();
    unsigned mx = 0;
#pragma unroll
    for (int w = 0; w < 8; ++w) mx = max(mx, ws[1][w]);

    // ---- dual-probe search (interpolation + bisection per iteration) ----
    // Counts for both probes packed into one 32-bit accumulator
    // (low 16 = p1, high 16 = p2; max count 2049 fits). Invariant:
    // cnt(>=lo) > 64 > cnt(>=hi).  cl = cnt(>=lo), ch = cnt(>=hi).
    unsigned lo = 0u, hi = mx + 1u, thr = 0u;
    unsigned cl = 2049u, ch = 0u;
    bool exact = false;
    int it = 0;
    while (hi - lo > 1u) {
        // probe a: interpolation; probe b: bisection (worst-case guarantee)
        unsigned range = hi - lo;
        float f = (float)(cl - TOPK) / (float)(cl - ch);
        unsigned pa = lo + (unsigned)((float)range * f);
        if (pa <= lo) pa = lo + 1u;
        if (pa >= hi) pa = hi - 1u;
        unsigned pb = lo + (range >> 1);
        unsigned p1 = min(pa, pb), p2 = max(pa, pb);
        if (p1 == p2) { if (p2 + 1u < hi) p2 = p2 + 1u; }
        unsigned v = 0;
#pragma unroll
        for (int q = 0; q < 9; ++q) {
            unsigned u = mv[q];
            v += (u >= p1) + ((unsigned)(u >= p2) << 16);
        }
        v = __reduce_add_sync(0xffffffffu, v);
        if ((tid & 31) == 0) ws[it & 1][tid >> 5] = v;
        __syncthreads();
        unsigned csum = 0;
#pragma unroll
        for (int w = 0; w < 8; ++w) csum += ws[it & 1][w];
        unsigned c1 = csum & 0xffffu, c2 = csum >> 16;   // c1 >= c2
        ++it;
        if (c1 == TOPK) { thr = p1; exact = true; break; }
        if (c2 == TOPK) { thr = p2; exact = true; break; }
        if (c1 < TOPK) {                 // 64th in [lo, p1)
            hi = p1; ch = c1;
        } else if (c2 > TOPK) {          // 64th in [p2, hi)
            lo = p2; cl = c2;
        } else {                         // c1 > 64 > c2: in [p1, p2)
            lo = p1; cl = c1;
            hi = p2; ch = c2;
        }
    }
    int need = 0;
    if (!exact) {
        thr = lo;                    // exact value of the 64th-largest
        need = TOPK - (int)ch;       // cnt(>thr) = cnt(>=hi) = ch; ties lowest-index-first
    }

    // ---- register-direct top-k masking of this thread's own bins ----
    // Phase 1: decide from registers (tie scans read X, no writes yet).
    bool k0 = decide_keep(X, mv[0], b0, thr, exact, need);
    bool k1 = decide_keep(X, mv[1], b1, thr, exact, need);
    bool k2 = decide_keep(X, mv[2], b2, thr, exact, need);
    bool k3 = decide_keep(X, mv[3], b3, thr, exact, need);
    bool k4 = decide_keep(X, mv[4], b4, thr, exact, need);
    bool k5 = decide_keep(X, mv[5], b5, thr, exact, need);
    bool k6 = decide_keep(X, mv[6], b6, thr, exact, need);
    bool k7 = decide_keep(X, mv[7], b7, thr, exact, need);
    bool k8 = (t == 0) ? decide_keep(X, mv[8], 1024, thr, exact, need) : true;
    __syncthreads();                 // all tie scans done before zeroing
    // Phase 2: zero non-kept bins in place.
    const float2 Z0 = make_float2(0.0f, 0.0f);
    if (!k0) X[b0] = Z0;
    if (!k1) X[b1] = Z0;
    if (!k2) X[b2] = Z0;
    if (!k3) X[b3] = Z0;
    if (!k4) X[b4] = Z0;
    if (!k5) X[b5] = Z0;
    if (!k6) X[b6] = Z0;
    if (!k7) X[b7] = Z0;
    if (t == 0 && !k8) X[1024] = Z0;
    __syncthreads();

    // ---- inverse FFT: Hermitian repack (X pre-masked) fused into first r8 ----
    {
        const int i = tid;
        const float2 HALF2 = make_float2(0.5f, 0.5f);
        float2 z[8], b[8];
#pragma unroll
        for (int m = 0; m < 8; ++m) {
            int k = i + 256 * m;
            float2 xk = X[k];
            float2 xc = X[2048 - k];
            xc.y = -xc.y;
            float2 fe = pmul(padd(xk, xc), HALF2);
            float2 d  = pmul(psub(xk, xc), HALF2);
            float2 fo = cmul(d, TW[k]);                     // * e^{+i 2pi k/4096}
            z[m] = make_float2(fe.x - fo.y, fe.y + fo.x);   // fe + i*fo
        }
        bfly8<true>(z, b);
        float2 w1 = TW[2 * i];
        const int o = 8 * i;
        SCATTER_W_TREE(Bb, o, 1, b, w1);
    }
    __syncthreads();
    r8_stage<8,  true>(Bb, A,  TW); __syncthreads();
    r8_stage<64, true>(A,  Bb, TW); __syncthreads();
    // final radix-4, L=512, twiddle-free, scaled, straight to global
    const float2 SC2 = make_float2(1.0f / 2048.0f, 1.0f / 2048.0f);
    float2* go = (float2*)rowp;
#pragma unroll
    for (int ii = 0; ii < 2; ++ii) {
        int i = tid + ii * NT;
        float2 a0 = Bb[SW(i)];
        float2 a1 = Bb[SW(i + 512)];
        float2 a2 = Bb[SW(i + 1024)];
        float2 a3 = Bb[SW(i + 1536)];
        float2 t0 = padd(a0, a2), t1 = psub(a0, a2);
        float2 t2 = padd(a1, a3), t3 = psub(a1, a3);
        float2 b0v = padd(t0, t2);
        float2 b1v = make_float2(t1.x - t3.y, t1.y + t3.x);  // t1 + i t3 (inverse)
        float2 b2v = psub(t0, t2);
        float2 b3v = make_float2(t1.x + t3.y, t1.y - t3.x);
        go[i]        = pmul(b0v, SC2);
        go[i + 512]  = pmul(b1v, SC2);
        go[i + 1024] = pmul(b2v, SC2);
        go[i + 1536] = pmul(b3v, SC2);
    }
}

// ---------------------------------------------------------------------------
extern "C" void kernel_launch(void* const* d_in, const int* in_sizes, int n_in,
                              void* d_out, int out_size) {
    const float* ts = (const float*)d_in[0];
    float* out = (float*)d_out;

    const int smem_bytes = 32800;
    cudaFuncSetAttribute(fft_topk_kernel,
                         cudaFuncAttributeMaxDynamicSharedMemorySize, smem_bytes);

    dim3 tblk(8, 32);
    init_tw_kernel<<<N2 / 256, 256>>>();
    transpose_in_kernel<<<dim3(C_DIM / 32, S_DIM / 32, B_DIM), tblk>>>(ts);
    fft_topk_kernel<<<B_DIM * C_DIM, NT, smem_bytes>>>();
    transpose_out_kernel<<<dim3(S_DIM / 32, C_DIM / 32, B_DIM), tblk>>>(out);
}

// round 16
// speedup vs baseline: 1.0773x; 1.0773x over previous
#include <cuda_runtime.h>
#include <math.h>

// Problem constants
#define B_DIM 64
#define S_DIM 4096
#define C_DIM 128
#define N2 2048          // half-length complex FFT size
#define NT 256
#define TOPK 64

// 128 MB scratch in (B, C, S) layout
__device__ float g_scratch[(size_t)B_DIM * C_DIM * S_DIM];
// Twiddle table in global: g_tw[t] = (cos(pi t/2048), sin(pi t/2048))
__device__ float2 g_tw[N2];

typedef unsigned long long u64;

__device__ __forceinline__ float2 cmul(float2 a, float2 b) {
    return make_float2(a.x * b.x - a.y * b.y, a.x * b.y + a.y * b.x);
}

// ---- packed f32x2 ops (Blackwell FADD2/FFMA2/FMUL2). Bit-identical per lane
// to the scalar versions (fma(b,-1,a) rounds once to the exact a-b). ----
__device__ __forceinline__ float2 padd(float2 a, float2 b) {
    u64 pa, pb, pc;
    asm("mov.b64 %0, {%1,%2};" : "=l"(pa) : "f"(a.x), "f"(a.y));
    asm("mov.b64 %0, {%1,%2};" : "=l"(pb) : "f"(b.x), "f"(b.y));
    asm("add.rn.f32x2 %0, %1, %2;" : "=l"(pc) : "l"(pa), "l"(pb));
    float2 r;
    asm("mov.b64 {%0,%1}, %2;" : "=f"(r.x), "=f"(r.y) : "l"(pc));
    return r;
}
__device__ __forceinline__ float2 psub(float2 a, float2 b) {
    u64 pa, pb, pc;
    asm("mov.b64 %0, {%1,%2};" : "=l"(pa) : "f"(a.x), "f"(a.y));
    asm("mov.b64 %0, {%1,%2};" : "=l"(pb) : "f"(b.x), "f"(b.y));
    asm("fma.rn.f32x2 %0, %1, %2, %3;"
        : "=l"(pc) : "l"(pb), "l"(0xBF800000BF800000ull), "l"(pa));
    float2 r;
    asm("mov.b64 {%0,%1}, %2;" : "=f"(r.x), "=f"(r.y) : "l"(pc));
    return r;
}
__device__ __forceinline__ float2 pmul(float2 a, float2 b) {
    u64 pa, pb, pc;
    asm("mov.b64 %0, {%1,%2};" : "=l"(pa) : "f"(a.x), "f"(a.y));
    asm("mov.b64 %0, {%1,%2};" : "=l"(pb) : "f"(b.x), "f"(b.y));
    asm("mul.rn.f32x2 %0, %1, %2;" : "=l"(pc) : "l"(pa), "l"(pb));
    float2 r;
    asm("mov.b64 {%0,%1}, %2;" : "=f"(r.x), "=f"(r.y) : "l"(pc));
    return r;
}

// Bank swizzle: bijective on [0,2048); conflict-free for all Stockham
// radix-8 patterns used here (stride-8 scatter, blocked scatter, consecutive).
__device__ __forceinline__ int SW(int i) { return i ^ (i >> 3); }

// Bit-exact mag^2 (used for both ranking values and the tie re-check).
__device__ __forceinline__ unsigned mag2u(float2 x) {
    return __float_as_uint(__fadd_rn(__fmul_rn(x.x, x.x), __fmul_rn(x.y, x.y)));
}

// ---------------------------------------------------------------------------
__global__ void __launch_bounds__(256) init_tw_kernel() {
    int t = blockIdx.x * 256 + threadIdx.x;
    float s, c;
    sincospif((float)t * (1.0f / 2048.0f), &s, &c);
    g_tw[t] = make_float2(c, s);
}

// ---------------------------------------------------------------------------
// Transposes, float4 on both global sides. At the structural HBM ceiling
// (~62% of spec) for this mixed gather/scatter pattern — leave alone.
// ---------------------------------------------------------------------------
__global__ void __launch_bounds__(256) transpose_in_kernel(const float* __restrict__ in) {
    __shared__ float tile[32][33];           // tile[channel][s]
    const int b = blockIdx.z;
    const int c0 = blockIdx.x * 32;          // channel tile
    const int r0 = blockIdx.y * 32;          // s tile
    const int tx = threadIdx.x;              // 0..7
    const int ty = threadIdx.y;              // 0..31
    const float* inb = in + (size_t)b * S_DIM * C_DIM;
    float* outb = g_scratch + (size_t)b * S_DIM * C_DIM;

    float4 v = *(const float4*)&inb[(size_t)(r0 + ty) * C_DIM + (c0 + 4 * tx)];
    tile[4 * tx + 0][ty] = v.x;
    tile[4 * tx + 1][ty] = v.y;
    tile[4 * tx + 2][ty] = v.z;
    tile[4 * tx + 3][ty] = v.w;
    __syncthreads();
    float4 w;
    w.x = tile[ty][4 * tx + 0];
    w.y = tile[ty][4 * tx + 1];
    w.z = tile[ty][4 * tx + 2];
    w.w = tile[ty][4 * tx + 3];
    *(float4*)&outb[(size_t)(c0 + ty) * S_DIM + (r0 + 4 * tx)] = w;
}

__global__ void __launch_bounds__(256) transpose_out_kernel(float* __restrict__ out) {
    __shared__ float tile[32][33];           // tile[s][channel]
    const int b = blockIdx.z;
    const int s0 = blockIdx.x * 32;          // s tile
    const int ch0 = blockIdx.y * 32;         // channel tile
    const int tx = threadIdx.x;              // 0..7
    const int ty = threadIdx.y;              // 0..31
    const float* inb = g_scratch + (size_t)b * S_DIM * C_DIM;
    float* outb = out + (size_t)b * S_DIM * C_DIM;

    float4 v = *(const float4*)&inb[(size_t)(ch0 + ty) * S_DIM + (s0 + 4 * tx)];
    tile[4 * tx + 0][ty] = v.x;
    tile[4 * tx + 1][ty] = v.y;
    tile[4 * tx + 2][ty] = v.z;
    tile[4 * tx + 3][ty] = v.w;
    __syncthreads();
    float4 w;
    w.x = tile[ty][4 * tx + 0];
    w.y = tile[ty][4 * tx + 1];
    w.z = tile[ty][4 * tx + 2];
    w.w = tile[ty][4 * tx + 3];
    *(float4*)&outb[(size_t)(s0 + ty) * C_DIM + (ch0 + 4 * tx)] = w;
}

// ---------------------------------------------------------------------------
// Radix-8 butterfly. Forward: omega = e^{-2pi i/8}; inverse: conjugate.
// Pure add/sub layers use packed f32x2 (bit-identical).
// ---------------------------------------------------------------------------
template<bool INV>
__device__ __forceinline__ void bfly8(const float2* a, float2* b) {
    const float r = 0.70710678118654752440f;
    float2 s0 = padd(a[0], a[4]), s1 = psub(a[0], a[4]);
    float2 s2 = padd(a[2], a[6]), s3 = psub(a[2], a[6]);
    float2 s4 = padd(a[1], a[5]), s5 = psub(a[1], a[5]);
    float2 s6 = padd(a[3], a[7]), s7 = psub(a[3], a[7]);
    float2 E0 = padd(s0, s2), E2 = psub(s0, s2);
    float2 O0 = padd(s4, s6), O2 = psub(s4, s6);
    float2 E1, E3, O1, O3;
    if (!INV) {
        E1 = make_float2(s1.x + s3.y, s1.y - s3.x);   // s1 - i s3
        E3 = make_float2(s1.x - s3.y, s1.y + s3.x);
        O1 = make_float2(s5.x + s7.y, s5.y - s7.x);
        O3 = make_float2(s5.x - s7.y, s5.y + s7.x);
    } else {
        E1 = make_float2(s1.x - s3.y, s1.y + s3.x);   // s1 + i s3
        E3 = make_float2(s1.x + s3.y, s1.y - s3.x);
        O1 = make_float2(s5.x - s7.y, s5.y + s7.x);
        O3 = make_float2(s5.x + s7.y, s5.y - s7.x);
    }
    b[0] = padd(E0, O0);
    b[4] = psub(E0, O0);
    float2 w1O, w3O;
    if (!INV) {
        w1O = make_float2(r * (O1.x + O1.y), r * (O1.y - O1.x));   // e^{-i pi/4} O1
        w3O = make_float2(r * (O3.y - O3.x), -r * (O3.x + O3.y));  // e^{-3i pi/4} O3
        b[2] = make_float2(E2.x + O2.y, E2.y - O2.x);              // E2 - i O2
        b[6] = make_float2(E2.x - O2.y, E2.y + O2.x);
    } else {
        w1O = make_float2(r * (O1.x - O1.y), r * (O1.x + O1.y));   // e^{+i pi/4} O1
        w3O = make_float2(-r * (O3.x + O3.y), r * (O3.x - O3.y));  // e^{+3i pi/4} O3
        b[2] = make_float2(E2.x - O2.y, E2.y + O2.x);              // E2 + i O2
        b[6] = make_float2(E2.x + O2.y, E2.y - O2.x);
    }
    b[1] = padd(E1, w1O);
    b[5] = psub(E1, w1O);
    b[3] = padd(E3, w3O);
    b[7] = psub(E3, w3O);
}

// Log-depth twiddle powers + scatter stores: dependency depth 3 cmuls.
#define SCATTER_W_TREE(dst, o, STRIDE, b, w1)                          \
    do {                                                               \
        float2 _w2 = cmul(w1, w1);                                     \
        float2 _w3 = cmul(_w2, w1);                                    \
        float2 _w4 = cmul(_w2, _w2);                                   \
        (dst)[SW((o))]              = (b)[0];                          \
        (dst)[SW((o) + (STRIDE))]   = cmul((b)[1], w1);                \
        (dst)[SW((o) + 2*(STRIDE))] = cmul((b)[2], _w2);               \
        (dst)[SW((o) + 3*(STRIDE))] = cmul((b)[3], _w3);               \
        (dst)[SW((o) + 4*(STRIDE))] = cmul((b)[4], _w4);               \
        (dst)[SW((o) + 5*(STRIDE))] = cmul((b)[5], cmul(_w4, w1));     \
        (dst)[SW((o) + 6*(STRIDE))] = cmul((b)[6], cmul(_w4, _w2));    \
        (dst)[SW((o) + 7*(STRIDE))] = cmul((b)[7], cmul(_w4, _w3));    \
    } while (0)

// Generic radix-8 Stockham stage, smem->smem, swizzled, one butterfly/thread.
template<int L, bool INV>
__device__ __forceinline__ void r8_stage(const float2* __restrict__ src,
                                         float2* __restrict__ dst,
                                         const float2* __restrict__ TW) {
    const int i = threadIdx.x;           // 256 butterflies
    const int k = i & (L - 1);
    const int u = i - k;
    float2 a[8], b[8];
#pragma unroll
    for (int m = 0; m < 8; ++m) a[m] = src[SW(i + 256 * m)];
    bfly8<INV>(a, b);
    float2 w1 = TW[2 * u];
    if (!INV) w1.y = -w1.y;
    const int o = 8 * u + k;
    SCATTER_W_TREE(dst, o, L, b, w1);
}

// First forward radix-8 stage (L=1), reading coalesced from global row.
__device__ __forceinline__ void r8_first_fwd(const float2* __restrict__ g,
                                             float2* __restrict__ dst,
                                             const float2* __restrict__ TW) {
    const int i = threadIdx.x;
    float2 a[8], b[8];
#pragma unroll
    for (int m = 0; m < 8; ++m) a[m] = g[i + 256 * m];
    bfly8<false>(a, b);
    float2 w1 = TW[2 * i]; w1.y = -w1.y;
    const int o = 8 * i;
    SCATTER_W_TREE(dst, o, 1, b, w1);
}

// Hermitian pair: given Z[k] (=a) and Z[2048-k] (=b), produce X[k], X[2048-k].
__device__ __forceinline__ void herm_pair(float2* __restrict__ X,
                                          const float2* __restrict__ TW,
                                          int k, float2 a, float2 b,
                                          unsigned& m1, unsigned& m2) {
    float2 fe = make_float2(0.5f * (a.x + b.x), 0.5f * (a.y - b.y));
    float2 d  = make_float2(0.5f * (a.x - b.x), 0.5f * (a.y + b.y));
    float2 w  = make_float2(TW[k].x, -TW[k].y);        // e^{-i 2pi k/4096}
    float2 wd = cmul(w, d);
    float2 x1 = make_float2(fe.x + wd.y, fe.y - wd.x);
    float2 x2 = make_float2(fe.x - wd.y, -fe.y - wd.x);
    X[k] = x1;
    X[2048 - k] = x2;
    m1 = mag2u(x1);
    m2 = mag2u(x2);
}

// Keep decision from the register-held mag^2 u of bin `bin`. Tie path reads X
// (unmodified at this point) for lowest-index-first rank, matching lax.top_k.
__device__ __forceinline__ bool decide_keep(const float2* __restrict__ X,
                                            unsigned u, int bin,
                                            unsigned thr, bool exact, int need) {
    if (exact) return u >= thr;
    if (u > thr) return true;
    if (u == thr) {
        int r = 0;
        for (int j = 0; j < bin; ++j)
            r += (mag2u(X[j]) == thr);
        return r < need;
    }
    return false;
}

// ---------------------------------------------------------------------------
// Per-row FFT + top-k + inverse FFT.
// Shared layout (dynamic, floats):
//   A  [2049 float2] @ 0      swizzled ping buffer; X aliases it identity-idx
//   Bb [2048 float2] @ 4098   swizzled pong buffer
// = 8194 floats = 32776 bytes.  Static: ws4[2][2] (vectorized warp sums).
// ---------------------------------------------------------------------------
__global__ void __launch_bounds__(NT, 5) fft_topk_kernel() {
    extern __shared__ float sh[];
    float2* A  = (float2*)sh;            // 2049 entries
    float2* Bb = (float2*)(sh + 4098);   // 2048 entries
    float2* X  = A;                      // identity-indexed (2049 entries)
    const float2* TW = g_tw;
    __shared__ uint4 ws4[2][2];          // 2 x 8 unsigned, LDS.128-readable
    unsigned* ws = (unsigned*)ws4;       // ws[row*8 + warp]

    const int tid = threadIdx.x;
    float* rowp = g_scratch + (size_t)blockIdx.x * S_DIM;
    const float2* gz = (const float2*)rowp;

    // ---- forward FFT: 3 radix-8 stages ----
    r8_first_fwd(gz, Bb, TW);        __syncthreads();
    r8_stage<8,  false>(Bb, A,  TW); __syncthreads();
    r8_stage<64, false>(A,  Bb, TW); __syncthreads();

    // ---- fused final radix-4 (twiddle-free) + Hermitian pair unpack ----
    // Thread t computes butterflies t and 512-t (t=0: 0 and 256); their 8
    // bins contain all four Hermitian pairs, so X is written from registers.
    unsigned mv[9];
#pragma unroll
    for (int q = 0; q < 9; ++q) mv[q] = 0u;
    unsigned vm = 0u;
    const int t = tid;
    // Bin indices owned by this thread (match herm_pair calls below).
    const int b0 = t;
    const int b1 = 2048 - t;
    const int b2 = t + 512;
    const int b3 = 1536 - t;
    const int b4 = (t == 0) ? 256  : 1024 - t;
    const int b5 = (t == 0) ? 1792 : 1024 + t;
    const int b6 = (t == 0) ? 768  : 512 - t;
    const int b7 = (t == 0) ? 1280 : 1536 + t;
    {
        const int bfa = t;
        const int bfb = (t == 0) ? 256 : 512 - t;
        float2 c0, c1, c2, c3, e0, e1, e2, e3;
        {
            float2 a0 = Bb[SW(bfa)],        a1 = Bb[SW(bfa + 512)],
                   a2 = Bb[SW(bfa + 1024)], a3 = Bb[SW(bfa + 1536)];
            float2 t0 = padd(a0, a2), t1 = psub(a0, a2);
            float2 t2 = padd(a1, a3), t3 = psub(a1, a3);
            c0 = padd(t0, t2);
            c1 = make_float2(t1.x + t3.y, t1.y - t3.x);   // t1 - i t3
            c2 = psub(t0, t2);
            c3 = make_float2(t1.x - t3.y, t1.y + t3.x);   // t1 + i t3
        }
        {
            float2 a0 = Bb[SW(bfb)],        a1 = Bb[SW(bfb + 512)],
                   a2 = Bb[SW(bfb + 1024)], a3 = Bb[SW(bfb + 1536)];
            float2 t0 = padd(a0, a2), t1 = psub(a0, a2);
            float2 t2 = padd(a1, a3), t3 = psub(a1, a3);
            e0 = padd(t0, t2);
            e1 = make_float2(t1.x + t3.y, t1.y - t3.x);
            e2 = psub(t0, t2);
            e3 = make_float2(t1.x - t3.y, t1.y + t3.x);
        }
        if (t > 0) {
            herm_pair(X, TW, t,        c0, e3, mv[0], mv[1]);
            herm_pair(X, TW, t + 512,  c1, e2, mv[2], mv[3]);
            herm_pair(X, TW, 1024 - t, e1, c2, mv[4], mv[5]);
            herm_pair(X, TW, 512 - t,  e0, c3, mv[6], mv[7]);
        } else {
            herm_pair(X, TW, 0,   c0, c0, mv[0], mv[1]);
            herm_pair(X, TW, 512, c1, c3, mv[2], mv[3]);
            herm_pair(X, TW, 256, e0, e3, mv[4], mv[5]);
            herm_pair(X, TW, 768, e1, e2, mv[6], mv[7]);
            float2 x = make_float2(c2.x, -c2.y);          // k=1024: conj(Z[1024])
            X[1024] = x;
            mv[8] = mag2u(x);
        }
#pragma unroll
        for (int q = 0; q < 9; ++q) vm = max(vm, mv[q]);
    }
    // block max seed (one barrier serves X writes + ws writes)
    vm = __reduce_max_sync(0xffffffffu, vm);
    if ((tid & 31) == 0) ws[8 + (tid >> 5)] = vm;
    __syncthreads();
    unsigned mx;
    {
        uint4 sa = ws4[1][0], sb = ws4[1][1];
        mx = max(max(max(sa.x, sa.y), max(sa.z, sa.w)),
                 max(max(sb.x, sb.y), max(sb.z, sb.w)));
    }

    // ---- safeguarded interpolation search for the 64th-largest mag^2 ----
    // Invariant: cnt(>=lo) > 64 > cnt(>=hi).  cl = cnt(>=lo), ch = cnt(>=hi).
    // Alternates interpolation (fast typical convergence) with bisection
    // (worst-case guarantee). All threads compute identical mid.
    unsigned lo = 0u, hi = mx + 1u, thr = 0u;
    unsigned cl = 2049u, ch = 0u;
    bool exact = false;
    int it = 0;
    while (hi - lo > 1u) {
        unsigned mid;
        if (it & 1) {
            mid = lo + ((hi - lo) >> 1);
        } else {
            float f = (float)(cl - TOPK) / (float)(cl - ch);
            unsigned off = (unsigned)((float)(hi - lo) * f);
            mid = lo + off;
            if (mid <= lo) mid = lo + 1u;
            if (mid >= hi) mid = hi - 1u;
        }
        unsigned v = 0;
#pragma unroll
        for (int q = 0; q < 9; ++q) v += (mv[q] >= mid);
        v = __reduce_add_sync(0xffffffffu, v);
        if ((tid & 31) == 0) ws[(it & 1) * 8 + (tid >> 5)] = v;
        __syncthreads();
        unsigned cnt;
        {
            uint4 sa = ws4[it & 1][0], sb = ws4[it & 1][1];
            cnt = sa.x + sa.y + sa.z + sa.w + sb.x + sb.y + sb.z + sb.w;
        }
        if (cnt == TOPK) { thr = mid; exact = true; break; }
        if (cnt > TOPK) { lo = mid; cl = cnt; } else { hi = mid; ch = cnt; }
        ++it;
    }
    int need = 0;
    if (!exact) {
        thr = lo;                    // exact value of the 64th-largest
        need = TOPK - (int)ch;       // cnt(>thr) = cnt(>=hi) = ch; ties lowest-index-first
    }

    // ---- register-direct top-k masking of this thread's own bins ----
    // Phase 1: decide from registers (tie scans read X, no writes yet).
    bool k0 = decide_keep(X, mv[0], b0, thr, exact, need);
    bool k1 = decide_keep(X, mv[1], b1, thr, exact, need);
    bool k2 = decide_keep(X, mv[2], b2, thr, exact, need);
    bool k3 = decide_keep(X, mv[3], b3, thr, exact, need);
    bool k4 = decide_keep(X, mv[4], b4, thr, exact, need);
    bool k5 = decide_keep(X, mv[5], b5, thr, exact, need);
    bool k6 = decide_keep(X, mv[6], b6, thr, exact, need);
    bool k7 = decide_keep(X, mv[7], b7, thr, exact, need);
    bool k8 = (t == 0) ? decide_keep(X, mv[8], 1024, thr, exact, need) : true;
    __syncthreads();                 // all tie scans done before zeroing
    // Phase 2: zero non-kept bins in place.
    const float2 Z0 = make_float2(0.0f, 0.0f);
    if (!k0) X[b0] = Z0;
    if (!k1) X[b1] = Z0;
    if (!k2) X[b2] = Z0;
    if (!k3) X[b3] = Z0;
    if (!k4) X[b4] = Z0;
    if (!k5) X[b5] = Z0;
    if (!k6) X[b6] = Z0;
    if (!k7) X[b7] = Z0;
    if (t == 0 && !k8) X[1024] = Z0;
    __syncthreads();

    // ---- inverse FFT: Hermitian repack (X pre-masked) fused into first r8 ----
    {
        const int i = tid;
        const float2 HALF2 = make_float2(0.5f, 0.5f);
        float2 z[8], b[8];
#pragma unroll
        for (int m = 0; m < 8; ++m) {
            int k = i + 256 * m;
            float2 xk = X[k];
            float2 xc = X[2048 - k];
            xc.y = -xc.y;
            float2 fe = pmul(padd(xk, xc), HALF2);
            float2 d  = pmul(psub(xk, xc), HALF2);
            float2 fo = cmul(d, TW[k]);                     // * e^{+i 2pi k/4096}
            z[m] = make_float2(fe.x - fo.y, fe.y + fo.x);   // fe + i*fo
        }
        bfly8<true>(z, b);
        float2 w1 = TW[2 * i];
        const int o = 8 * i;
        SCATTER_W_TREE(Bb, o, 1, b, w1);
    }
    __syncthreads();
    r8_stage<8,  true>(Bb, A,  TW); __syncthreads();
    r8_stage<64, true>(A,  Bb, TW); __syncthreads();
    // final radix-4, L=512, twiddle-free, scaled, straight to global
    const float2 SC2 = make_float2(1.0f / 2048.0f, 1.0f / 2048.0f);
    float2* go = (float2*)rowp;
#pragma unroll
    for (int ii = 0; ii < 2; ++ii) {
        int i = tid + ii * NT;
        float2 a0 = Bb[SW(i)];
        float2 a1 = Bb[SW(i + 512)];
        float2 a2 = Bb[SW(i + 1024)];
        float2 a3 = Bb[SW(i + 1536)];
        float2 t0 = padd(a0, a2), t1 = psub(a0, a2);
        float2 t2 = padd(a1, a3), t3 = psub(a1, a3);
        float2 b0v = padd(t0, t2);
        float2 b1v = make_float2(t1.x - t3.y, t1.y + t3.x);  // t1 + i t3 (inverse)
        float2 b2v = psub(t0, t2);
        float2 b3v = make_float2(t1.x + t3.y, t1.y - t3.x);
        go[i]        = pmul(b0v, SC2);
        go[i + 512]  = pmul(b1v, SC2);
        go[i + 1024] = pmul(b2v, SC2);
        go[i + 1536] = pmul(b3v, SC2);
    }
}

// ---------------------------------------------------------------------------
extern "C" void kernel_launch(void* const* d_in, const int* in_sizes, int n_in,
                              void* d_out, int out_size) {
    const float* ts = (const float*)d_in[0];
    float* out = (float*)d_out;

    const int smem_bytes = 32800;
    cudaFuncSetAttribute(fft_topk_kernel,
                         cudaFuncAttributeMaxDynamicSharedMemorySize, smem_bytes);

    dim3 tblk(8, 32);
    init_tw_kernel<<<N2 / 256, 256>>>();
    transpose_in_kernel<<<dim3(C_DIM / 32, S_DIM / 32, B_DIM), tblk>>>(ts);
    fft_topk_kernel<<<B_DIM * C_DIM, NT, smem_bytes>>>();
    transpose_out_kernel<<<dim3(S_DIM / 32, C_DIM / 32, B_DIM), tblk>>>(out);
}